// round 2
// baseline (speedup 1.0000x reference)
#include <cuda_runtime.h>
#include <math.h>

// Problem constants (fixed by the dataset)
#define BB 4
#define NN 2048
#define CC 1024
#define HH 16
#define HD 64
#define LR 20
#define RR 200
#define M_TOK (BB * NN)   // 8192 token rows

// Scratch (allocation-free rule: __device__ globals)
__device__ float g_qk[(size_t)M_TOK * 2 * CC];   // [8192][2048]  q|k per row
__device__ float g_attn[(size_t)M_TOK * CC];     // [8192][1024]
__device__ float g_AE[(size_t)BB * HH * HD * HD];
__device__ float g_AR[(size_t)BB * HH * HD * HD];

// ---------------------------------------------------------------------------
// SGEMM: C[M,Nc] = A[M,K] @ B[Nc,K]^T (+ bias[Nc])
// 128x128 tile, BK=16, 256 threads, 8x8 per thread.
// ---------------------------------------------------------------------------
template <bool BIAS>
__global__ __launch_bounds__(256, 2) void sgemm_nt(
    const float* __restrict__ A, const float* __restrict__ B,
    const float* __restrict__ bias, float* __restrict__ C,
    int M, int Nc, int K)
{
    __shared__ float As[16][128];
    __shared__ float Bs[16][128];

    const int tid = threadIdx.x;
    const int bm = blockIdx.y * 128;
    const int bn = blockIdx.x * 128;
    const int tx = tid & 15;        // 16 col threads
    const int ty = tid >> 4;        // 16 row threads

    // loader mapping: 512 float4 per operand tile; thread covers rows r and r+64
    const int lrow = tid >> 2;            // 0..63
    const int lk4  = (tid & 3) * 4;       // 0,4,8,12

    const float* Ap = A + (size_t)(bm + lrow) * K + lk4;
    const float* Bp = B + (size_t)(bn + lrow) * K + lk4;

    float acc[8][8];
#pragma unroll
    for (int i = 0; i < 8; i++)
#pragma unroll
        for (int j = 0; j < 8; j++) acc[i][j] = 0.f;

    for (int kt = 0; kt < K; kt += 16) {
        float4 a0 = *(const float4*)(Ap + kt);
        float4 a1 = *(const float4*)(Ap + (size_t)64 * K + kt);
        float4 b0 = *(const float4*)(Bp + kt);
        float4 b1 = *(const float4*)(Bp + (size_t)64 * K + kt);

        __syncthreads();   // previous tile's compute done before overwrite
        As[lk4 + 0][lrow] = a0.x; As[lk4 + 1][lrow] = a0.y;
        As[lk4 + 2][lrow] = a0.z; As[lk4 + 3][lrow] = a0.w;
        As[lk4 + 0][lrow + 64] = a1.x; As[lk4 + 1][lrow + 64] = a1.y;
        As[lk4 + 2][lrow + 64] = a1.z; As[lk4 + 3][lrow + 64] = a1.w;
        Bs[lk4 + 0][lrow] = b0.x; Bs[lk4 + 1][lrow] = b0.y;
        Bs[lk4 + 2][lrow] = b0.z; Bs[lk4 + 3][lrow] = b0.w;
        Bs[lk4 + 0][lrow + 64] = b1.x; Bs[lk4 + 1][lrow + 64] = b1.y;
        Bs[lk4 + 2][lrow + 64] = b1.z; Bs[lk4 + 3][lrow + 64] = b1.w;
        __syncthreads();

#pragma unroll
        for (int k = 0; k < 16; k++) {
            float4 av0 = *(const float4*)&As[k][ty * 8];
            float4 av1 = *(const float4*)&As[k][ty * 8 + 4];
            float4 bv0 = *(const float4*)&Bs[k][tx * 8];
            float4 bv1 = *(const float4*)&Bs[k][tx * 8 + 4];
            float av[8] = {av0.x, av0.y, av0.z, av0.w, av1.x, av1.y, av1.z, av1.w};
            float bv[8] = {bv0.x, bv0.y, bv0.z, bv0.w, bv1.x, bv1.y, bv1.z, bv1.w};
#pragma unroll
            for (int i = 0; i < 8; i++)
#pragma unroll
                for (int j = 0; j < 8; j++) acc[i][j] += av[i] * bv[j];
        }
    }

    float bia[8];
    if (BIAS) {
#pragma unroll
        for (int j = 0; j < 8; j++) bia[j] = bias[bn + tx * 8 + j];
    }

#pragma unroll
    for (int i = 0; i < 8; i++) {
        int row = bm + ty * 8 + i;
        float* cp = C + (size_t)row * Nc + bn + tx * 8;
        float4 v0, v1;
        if (BIAS) {
            v0 = make_float4(acc[i][0] + bia[0], acc[i][1] + bia[1],
                             acc[i][2] + bia[2], acc[i][3] + bia[3]);
            v1 = make_float4(acc[i][4] + bia[4], acc[i][5] + bia[5],
                             acc[i][6] + bia[6], acc[i][7] + bia[7]);
        } else {
            v0 = make_float4(acc[i][0], acc[i][1], acc[i][2], acc[i][3]);
            v1 = make_float4(acc[i][4], acc[i][5], acc[i][6], acc[i][7]);
        }
        *(float4*)cp = v0;
        *(float4*)(cp + 4) = v1;
    }
}

// ---------------------------------------------------------------------------
// In-place L2 normalize every contiguous 64-float group of g_qk.
// One warp per group.
// ---------------------------------------------------------------------------
__global__ __launch_bounds__(256) void l2norm_kernel(float* __restrict__ g)
{
    int gidx = blockIdx.x * 8 + (threadIdx.x >> 5);
    int lane = threadIdx.x & 31;
    float* p = g + (size_t)gidx * 64;
    float v0 = p[lane];
    float v1 = p[lane + 32];
    float s = v0 * v0 + v1 * v1;
#pragma unroll
    for (int off = 16; off; off >>= 1) s += __shfl_xor_sync(0xffffffffu, s, off);
    float inv = 1.0f / fmaxf(sqrtf(s), 1e-12f);
    p[lane] = v0 * inv;
    p[lane + 32] = v1 * inv;
}

// ---------------------------------------------------------------------------
// Per (b,h): we_b/wr_b from 200 subsampled positions, folded with cw_w into
// AE[d][o] = sum_e we_b[d][e] * cw_w[o][e]
// AR[d][o] = sum_e wr_b[d][e] * cw_w[o][LR+e]
// ---------------------------------------------------------------------------
__global__ __launch_bounds__(256) void genw_kernel(
    const float* __restrict__ x, const float* __restrict__ we,
    const float* __restrict__ wr, const float* __restrict__ cw_w)
{
    int bh = blockIdx.x;            // b*16 + h
    int b = bh >> 4, h = bh & 15;
    __shared__ int   idx_s[RR];
    __shared__ float web[HD][LR], wrb[HD][LR];
    int t = threadIdx.x;

    if (t < RR) idx_s[t] = (int)((double)t * (double)(NN - 1) / (double)(RR - 1));
    __syncthreads();

    for (int it = t; it < HD * LR; it += 256) {
        int d = it / LR, e = it % LR;
        float se = 0.f, sr = 0.f;
        for (int r = 0; r < RR; r++) {
            float xv = x[((size_t)b * NN + idx_s[r]) * CC + h * HD + d];
            se += xv * we[((size_t)h * RR + r) * LR + e];
            sr += xv * wr[((size_t)h * RR + r) * LR + e];
        }
        web[d][e] = se;
        wrb[d][e] = sr;
    }
    __syncthreads();

    for (int it = t; it < HD * HD; it += 256) {
        int d = it >> 6, o = it & 63;
        float ae = 0.f, ar = 0.f;
#pragma unroll
        for (int e = 0; e < LR; e++) {
            ae += web[d][e] * cw_w[o * (2 * LR) + e];
            ar += wrb[d][e] * cw_w[o * (2 * LR) + LR + e];
        }
        size_t base = ((size_t)bh * HD + d) * HD + o;
        g_AE[base] = ae;
        g_AR[base] = ar;
    }
}

// ---------------------------------------------------------------------------
// attn[b,n,h*64+o] = cw_b[o] + sum_d q[d]*AE[d][o] + k[d]*AR[d][o]
// block = (b,h, 32 tokens); thread = (token, 8 output cols)
// ---------------------------------------------------------------------------
__global__ __launch_bounds__(256) void score_kernel(const float* __restrict__ cw_b)
{
    const int NT = NN / 32;         // 64
    int nt = blockIdx.x % NT;
    int bh = blockIdx.x / NT;
    int b = bh >> 4, h = bh & 15;

    __shared__ float AEs[HD][HD];
    __shared__ float ARs[HD][HD];
    __shared__ float cb[HD];

    int t = threadIdx.x;
    const float* gAE = g_AE + (size_t)bh * HD * HD;
    const float* gAR = g_AR + (size_t)bh * HD * HD;
    for (int i = t; i < HD * HD; i += 256) {
        ((float*)AEs)[i] = gAE[i];
        ((float*)ARs)[i] = gAR[i];
    }
    if (t < HD) cb[t] = cw_b[t];
    __syncthreads();

    int nl = t >> 3;                // 0..31
    int o8 = (t & 7) * 8;
    int n = nt * 32 + nl;

    const float* qrow = g_qk + ((size_t)(b * NN + n)) * (2 * CC) + h * HD;
    const float* krow = qrow + CC;

    float acc[8];
#pragma unroll
    for (int j = 0; j < 8; j++) acc[j] = cb[o8 + j];

#pragma unroll 8
    for (int d = 0; d < HD; d++) {
        float qd = qrow[d];
        float kd = krow[d];
        float4 e0 = *(const float4*)&AEs[d][o8];
        float4 e1 = *(const float4*)&AEs[d][o8 + 4];
        float4 r0 = *(const float4*)&ARs[d][o8];
        float4 r1 = *(const float4*)&ARs[d][o8 + 4];
        acc[0] += qd * e0.x + kd * r0.x;
        acc[1] += qd * e0.y + kd * r0.y;
        acc[2] += qd * e0.z + kd * r0.z;
        acc[3] += qd * e0.w + kd * r0.w;
        acc[4] += qd * e1.x + kd * r1.x;
        acc[5] += qd * e1.y + kd * r1.y;
        acc[6] += qd * e1.z + kd * r1.z;
        acc[7] += qd * e1.w + kd * r1.w;
    }

    float* out = g_attn + ((size_t)(b * NN + n)) * CC + h * HD + o8;
    *(float4*)out = make_float4(acc[0], acc[1], acc[2], acc[3]);
    *(float4*)(out + 4) = make_float4(acc[4], acc[5], acc[6], acc[7]);
}

// ---------------------------------------------------------------------------
extern "C" void kernel_launch(void* const* d_in, const int* in_sizes, int n_in,
                              void* d_out, int out_size)
{
    const float* x      = (const float*)d_in[0];
    const float* qk_w   = (const float*)d_in[1];
    const float* proj_w = (const float*)d_in[2];
    const float* proj_b = (const float*)d_in[3];
    const float* we     = (const float*)d_in[4];
    const float* wr     = (const float*)d_in[5];
    const float* cw_w   = (const float*)d_in[6];
    const float* cw_b   = (const float*)d_in[7];
    float* out = (float*)d_out;

    void* qk_ptr = nullptr;
    void* attn_ptr = nullptr;
    cudaGetSymbolAddress(&qk_ptr, g_qk);
    cudaGetSymbolAddress(&attn_ptr, g_attn);
    float* qk = (float*)qk_ptr;
    float* attn = (float*)attn_ptr;

    // 1) qk = x @ qk_w^T   [8192 x 2048]
    sgemm_nt<false><<<dim3(2 * CC / 128, M_TOK / 128), 256>>>(
        x, qk_w, nullptr, qk, M_TOK, 2 * CC, CC);

    // 2) per-64 L2 normalize (q and k heads) in place
    {
        int groups = M_TOK * 2 * CC / 64;   // 262144
        l2norm_kernel<<<groups / 8, 256>>>(qk);
    }

    // 3) fold subsampled low-rank weights into per-(b,h) 64x64 AE/AR
    genw_kernel<<<BB * HH, 256>>>(x, we, wr, cw_w);

    // 4) attn = q@AE + k@AR + cw_b
    score_kernel<<<BB * HH * (NN / 32), 256>>>(cw_b);

    // 5) out = attn @ proj_w^T + proj_b
    sgemm_nt<true><<<dim3(CC / 128, M_TOK / 128), 256>>>(
        attn, proj_w, proj_b, out, M_TOK, CC, CC);
}

// round 4
// speedup vs baseline: 1.0979x; 1.0979x over previous
#include <cuda_runtime.h>
#include <math.h>

// Problem constants (fixed by the dataset)
#define BB 4
#define NN 2048
#define CC 1024
#define HH 16
#define HD 64
#define LR 20
#define RR 200
#define M_TOK (BB * NN)   // 8192 token rows

typedef unsigned long long u64;

// Scratch (allocation-free rule: __device__ globals)
__device__ float g_qk[(size_t)M_TOK * 2 * CC];   // [8192][2048]  q|k per row
__device__ float g_attn[(size_t)M_TOK * CC];     // [8192][1024]
__device__ float g_AE[(size_t)BB * HH * HD * HD];
__device__ float g_AR[(size_t)BB * HH * HD * HD];

// ---------------- packed f32x2 helpers (FFMA2 on sm_103a) -------------------
__device__ __forceinline__ u64 dupf(float v) {
    u64 r; asm("mov.b64 %0, {%1, %1};" : "=l"(r) : "f"(v)); return r;
}
__device__ __forceinline__ void ffma2(u64& d, u64 a, u64 b) {
    asm("fma.rn.f32x2 %0, %1, %2, %0;" : "+l"(d) : "l"(a), "l"(b));
}
__device__ __forceinline__ float2 unpk(u64 v) {
    float2 f; asm("mov.b64 {%0, %1}, %2;" : "=f"(f.x), "=f"(f.y) : "l"(v)); return f;
}

// ---------------------------------------------------------------------------
// SGEMM: C[M,Nc] = A[M,K] @ B[Nc,K]^T (+ bias[Nc])
// 128x128 tile, BK=16, 256 threads, 8x8 per thread, FFMA2 inner loop.
// ---------------------------------------------------------------------------
template <bool BIAS>
__global__ __launch_bounds__(256, 2) void sgemm_nt(
    const float* __restrict__ A, const float* __restrict__ B,
    const float* __restrict__ bias, float* __restrict__ C,
    int M, int Nc, int K)
{
    __shared__ float As[16][128];
    __shared__ float Bs[16][128];

    const int tid = threadIdx.x;
    const int bm = blockIdx.y * 128;
    const int bn = blockIdx.x * 128;
    const int tx = tid & 15;        // 16 col threads
    const int ty = tid >> 4;        // 16 row threads

    const int lrow = tid >> 2;            // 0..63
    const int lk4  = (tid & 3) * 4;       // 0,4,8,12

    const float* Ap = A + (size_t)(bm + lrow) * K + lk4;
    const float* Bp = B + (size_t)(bn + lrow) * K + lk4;

    u64 acc[8][4];
#pragma unroll
    for (int i = 0; i < 8; i++)
#pragma unroll
        for (int j = 0; j < 4; j++) acc[i][j] = 0ull;

    for (int kt = 0; kt < K; kt += 16) {
        float4 a0 = *(const float4*)(Ap + kt);
        float4 a1 = *(const float4*)(Ap + (size_t)64 * K + kt);
        float4 b0 = *(const float4*)(Bp + kt);
        float4 b1 = *(const float4*)(Bp + (size_t)64 * K + kt);

        __syncthreads();   // previous tile's compute done before overwrite
        As[lk4 + 0][lrow] = a0.x; As[lk4 + 1][lrow] = a0.y;
        As[lk4 + 2][lrow] = a0.z; As[lk4 + 3][lrow] = a0.w;
        As[lk4 + 0][lrow + 64] = a1.x; As[lk4 + 1][lrow + 64] = a1.y;
        As[lk4 + 2][lrow + 64] = a1.z; As[lk4 + 3][lrow + 64] = a1.w;
        Bs[lk4 + 0][lrow] = b0.x; Bs[lk4 + 1][lrow] = b0.y;
        Bs[lk4 + 2][lrow] = b0.z; Bs[lk4 + 3][lrow] = b0.w;
        Bs[lk4 + 0][lrow + 64] = b1.x; Bs[lk4 + 1][lrow + 64] = b1.y;
        Bs[lk4 + 2][lrow + 64] = b1.z; Bs[lk4 + 3][lrow + 64] = b1.w;
        __syncthreads();

#pragma unroll
        for (int k = 0; k < 16; k++) {
            float4 av0 = *(const float4*)&As[k][ty * 8];
            float4 av1 = *(const float4*)&As[k][ty * 8 + 4];
            const ulonglong2* brow = (const ulonglong2*)&Bs[k][tx * 8];
            ulonglong2 bp0 = brow[0];     // pairs (b0,b1) (b2,b3)
            ulonglong2 bp1 = brow[1];     // pairs (b4,b5) (b6,b7)
            float av[8] = {av0.x, av0.y, av0.z, av0.w, av1.x, av1.y, av1.z, av1.w};
#pragma unroll
            for (int i = 0; i < 8; i++) {
                u64 ad = dupf(av[i]);
                ffma2(acc[i][0], ad, bp0.x);
                ffma2(acc[i][1], ad, bp0.y);
                ffma2(acc[i][2], ad, bp1.x);
                ffma2(acc[i][3], ad, bp1.y);
            }
        }
    }

    float bia[8];
    if (BIAS) {
#pragma unroll
        for (int j = 0; j < 8; j++) bia[j] = bias[bn + tx * 8 + j];
    }

#pragma unroll
    for (int i = 0; i < 8; i++) {
        int row = bm + ty * 8 + i;
        float* cp = C + (size_t)row * Nc + bn + tx * 8;
        float2 p0 = unpk(acc[i][0]);
        float2 p1 = unpk(acc[i][1]);
        float2 p2 = unpk(acc[i][2]);
        float2 p3 = unpk(acc[i][3]);
        float4 v0, v1;
        if (BIAS) {
            v0 = make_float4(p0.x + bia[0], p0.y + bia[1], p1.x + bia[2], p1.y + bia[3]);
            v1 = make_float4(p2.x + bia[4], p2.y + bia[5], p3.x + bia[6], p3.y + bia[7]);
        } else {
            v0 = make_float4(p0.x, p0.y, p1.x, p1.y);
            v1 = make_float4(p2.x, p2.y, p3.x, p3.y);
        }
        *(float4*)cp = v0;
        *(float4*)(cp + 4) = v1;
    }
}

// ---------------------------------------------------------------------------
// In-place L2 normalize every contiguous 64-float group of g_qk.
// One warp per group.
// ---------------------------------------------------------------------------
__global__ __launch_bounds__(256) void l2norm_kernel(float* __restrict__ g)
{
    int gidx = blockIdx.x * 8 + (threadIdx.x >> 5);
    int lane = threadIdx.x & 31;
    float* p = g + (size_t)gidx * 64;
    float v0 = p[lane];
    float v1 = p[lane + 32];
    float s = v0 * v0 + v1 * v1;
#pragma unroll
    for (int off = 16; off; off >>= 1) s += __shfl_xor_sync(0xffffffffu, s, off);
    float inv = 1.0f / fmaxf(sqrtf(s), 1e-12f);
    p[lane] = v0 * inv;
    p[lane + 32] = v1 * inv;
}

// ---------------------------------------------------------------------------
// Per (b,h): we_b/wr_b from 200 subsampled positions, folded with cw_w into
// AE[d][o], AR[d][o]  (64x64 each per (b,h))
// ---------------------------------------------------------------------------
__global__ __launch_bounds__(256) void genw_kernel(
    const float* __restrict__ x, const float* __restrict__ we,
    const float* __restrict__ wr, const float* __restrict__ cw_w)
{
    int bh = blockIdx.x;            // b*16 + h
    int b = bh >> 4, h = bh & 15;
    __shared__ int   idx_s[RR];
    __shared__ float web[HD][LR], wrb[HD][LR];
    int t = threadIdx.x;

    if (t < RR) idx_s[t] = (int)((double)t * (double)(NN - 1) / (double)(RR - 1));
    __syncthreads();

    for (int it = t; it < HD * LR; it += 256) {
        int d = it / LR, e = it % LR;
        float se = 0.f, sr = 0.f;
        for (int r = 0; r < RR; r++) {
            float xv = x[((size_t)b * NN + idx_s[r]) * CC + h * HD + d];
            se += xv * we[((size_t)h * RR + r) * LR + e];
            sr += xv * wr[((size_t)h * RR + r) * LR + e];
        }
        web[d][e] = se;
        wrb[d][e] = sr;
    }
    __syncthreads();

    for (int it = t; it < HD * HD; it += 256) {
        int d = it >> 6, o = it & 63;
        float ae = 0.f, ar = 0.f;
#pragma unroll
        for (int e = 0; e < LR; e++) {
            ae += web[d][e] * cw_w[o * (2 * LR) + e];
            ar += wrb[d][e] * cw_w[o * (2 * LR) + LR + e];
        }
        size_t base = ((size_t)bh * HD + d) * HD + o;
        g_AE[base] = ae;
        g_AR[base] = ar;
    }
}

// ---------------------------------------------------------------------------
// score v2: attn[b,n,h*64+o] = cw_b[o] + sum_d q[d]*AE[d][o] + k[d]*AR[d][o]
// Block = (64-token tile, bh). Q/K staged transposed (d-major) in smem.
// Thread = 2 tokens x 8 cols, FFMA2 inner loop.
// Dynamic smem: AEs 16KB | ARs 16KB | Qt 16KB | Kt 16KB = 64KB.
// ---------------------------------------------------------------------------
__global__ __launch_bounds__(256) void score_kernel(const float* __restrict__ cw_b)
{
    extern __shared__ float sm[];
    float* AEs = sm;               // [d][o]  64x64
    float* ARs = sm + 4096;        // [d][o]
    float* Qt  = sm + 8192;        // [d][tok] 64x64
    float* Kt  = sm + 12288;       // [d][tok]

    const int nt = blockIdx.x;     // 32 token tiles of 64
    const int bh = blockIdx.y;     // 64
    const int b = bh >> 4, h = bh & 15;
    const int t = threadIdx.x;

    // stage AE/AR (straight copy, layouts match)
    const float4* gAE = (const float4*)(g_AE + (size_t)bh * HD * HD);
    const float4* gAR = (const float4*)(g_AR + (size_t)bh * HD * HD);
#pragma unroll
    for (int i = t; i < 1024; i += 256) {
        ((float4*)AEs)[i] = gAE[i];
        ((float4*)ARs)[i] = gAR[i];
    }

    // stage Q/K transposed: Qt[d][tok]
#pragma unroll
    for (int i = t; i < 1024; i += 256) {
        int tt = i & 63;
        int d4 = (i >> 6) << 2;
        const float* qrow = g_qk + ((size_t)(b * NN + nt * 64 + tt)) * (2 * CC) + h * HD;
        float4 qv = *(const float4*)(qrow + d4);
        float4 kv = *(const float4*)(qrow + CC + d4);
        Qt[(d4 + 0) * 64 + tt] = qv.x; Qt[(d4 + 1) * 64 + tt] = qv.y;
        Qt[(d4 + 2) * 64 + tt] = qv.z; Qt[(d4 + 3) * 64 + tt] = qv.w;
        Kt[(d4 + 0) * 64 + tt] = kv.x; Kt[(d4 + 1) * 64 + tt] = kv.y;
        Kt[(d4 + 2) * 64 + tt] = kv.z; Kt[(d4 + 3) * 64 + tt] = kv.w;
    }
    __syncthreads();

    const int tg = t >> 3;          // 0..31 -> token pair
    const int o8 = (t & 7) * 8;     // col group
    const int t0 = tg * 2, t1 = t0 + 1;

    u64 acc0[4] = {0ull, 0ull, 0ull, 0ull};
    u64 acc1[4] = {0ull, 0ull, 0ull, 0ull};

#pragma unroll 8
    for (int d = 0; d < HD; d++) {
        u64 q0 = dupf(Qt[d * 64 + t0]);
        u64 q1 = dupf(Qt[d * 64 + t1]);
        u64 k0 = dupf(Kt[d * 64 + t0]);
        u64 k1 = dupf(Kt[d * 64 + t1]);
        ulonglong2 e01 = *(const ulonglong2*)&AEs[d * 64 + o8];
        ulonglong2 e23 = *(const ulonglong2*)&AEs[d * 64 + o8 + 4];
        ulonglong2 r01 = *(const ulonglong2*)&ARs[d * 64 + o8];
        ulonglong2 r23 = *(const ulonglong2*)&ARs[d * 64 + o8 + 4];
        ffma2(acc0[0], q0, e01.x); ffma2(acc0[1], q0, e01.y);
        ffma2(acc0[2], q0, e23.x); ffma2(acc0[3], q0, e23.y);
        ffma2(acc1[0], q1, e01.x); ffma2(acc1[1], q1, e01.y);
        ffma2(acc1[2], q1, e23.x); ffma2(acc1[3], q1, e23.y);
        ffma2(acc0[0], k0, r01.x); ffma2(acc0[1], k0, r01.y);
        ffma2(acc0[2], k0, r23.x); ffma2(acc0[3], k0, r23.y);
        ffma2(acc1[0], k1, r01.x); ffma2(acc1[1], k1, r01.y);
        ffma2(acc1[2], k1, r23.x); ffma2(acc1[3], k1, r23.y);
    }

    float cb0 = cw_b[o8 + 0], cb1 = cw_b[o8 + 1], cb2 = cw_b[o8 + 2], cb3 = cw_b[o8 + 3];
    float cb4 = cw_b[o8 + 4], cb5 = cw_b[o8 + 5], cb6 = cw_b[o8 + 6], cb7 = cw_b[o8 + 7];

    int nbase = nt * 64;
    {
        float2 p0 = unpk(acc0[0]), p1 = unpk(acc0[1]), p2 = unpk(acc0[2]), p3 = unpk(acc0[3]);
        float* out = g_attn + ((size_t)(b * NN + nbase + t0)) * CC + h * HD + o8;
        *(float4*)out = make_float4(p0.x + cb0, p0.y + cb1, p1.x + cb2, p1.y + cb3);
        *(float4*)(out + 4) = make_float4(p2.x + cb4, p2.y + cb5, p3.x + cb6, p3.y + cb7);
    }
    {
        float2 p0 = unpk(acc1[0]), p1 = unpk(acc1[1]), p2 = unpk(acc1[2]), p3 = unpk(acc1[3]);
        float* out = g_attn + ((size_t)(b * NN + nbase + t1)) * CC + h * HD + o8;
        *(float4*)out = make_float4(p0.x + cb0, p0.y + cb1, p1.x + cb2, p1.y + cb3);
        *(float4*)(out + 4) = make_float4(p2.x + cb4, p2.y + cb5, p3.x + cb6, p3.y + cb7);
    }
}

// ---------------------------------------------------------------------------
extern "C" void kernel_launch(void* const* d_in, const int* in_sizes, int n_in,
                              void* d_out, int out_size)
{
    const float* x      = (const float*)d_in[0];
    const float* qk_w   = (const float*)d_in[1];
    const float* proj_w = (const float*)d_in[2];
    const float* proj_b = (const float*)d_in[3];
    const float* we     = (const float*)d_in[4];
    const float* wr     = (const float*)d_in[5];
    const float* cw_w   = (const float*)d_in[6];
    const float* cw_b   = (const float*)d_in[7];
    float* out = (float*)d_out;

    void* qk_ptr = nullptr;
    void* attn_ptr = nullptr;
    cudaGetSymbolAddress(&qk_ptr, g_qk);
    cudaGetSymbolAddress(&attn_ptr, g_attn);
    float* qk = (float*)qk_ptr;
    float* attn = (float*)attn_ptr;

    // allow 64KB dynamic smem for score_kernel (idempotent, host-side, capture-safe)
    cudaFuncSetAttribute(score_kernel, cudaFuncAttributeMaxDynamicSharedMemorySize, 65536);

    // 1) qk = x @ qk_w^T   [8192 x 2048]
    sgemm_nt<false><<<dim3(2 * CC / 128, M_TOK / 128), 256>>>(
        x, qk_w, nullptr, qk, M_TOK, 2 * CC, CC);

    // 2) per-64 L2 normalize (q and k heads) in place
    {
        int groups = M_TOK * 2 * CC / 64;   // 262144
        l2norm_kernel<<<groups / 8, 256>>>(qk);
    }

    // 3) fold subsampled low-rank weights into per-(b,h) 64x64 AE/AR
    genw_kernel<<<BB * HH, 256>>>(x, we, wr, cw_w);

    // 4) attn = q@AE + k@AR + cw_b
    score_kernel<<<dim3(NN / 64, BB * HH), 256, 65536>>>(cw_b);

    // 5) out = attn @ proj_w^T + proj_b
    sgemm_nt<true><<<dim3(CC / 128, M_TOK / 128), 256>>>(
        attn, proj_w, proj_b, out, M_TOK, CC, CC);
}

// round 7
// speedup vs baseline: 2.2322x; 2.0331x over previous
#include <cuda_runtime.h>
#include <cuda_bf16.h>
#include <cstdint>
#include <stdint.h>
#include <math.h>

// Problem constants (fixed by the dataset)
#define BB 4
#define NN 2048
#define CC 1024
#define HH 16
#define HD 64
#define LR 20
#define RR 200
#define M_TOK (BB * NN)   // 8192 token rows

typedef unsigned long long u64;

// ---------------- scratch (__device__ globals; no allocs allowed) -----------
__device__ float g_qk[(size_t)M_TOK * 2 * CC];   // [8192][2048] q|k fp32
__device__ float g_attn[(size_t)M_TOK * CC];     // [8192][1024] fp32
__device__ float g_AE[(size_t)BB * HH * HD * HD];
__device__ float g_AR[(size_t)BB * HH * HD * HD];

__device__ __nv_bfloat16 g_xh[(size_t)M_TOK * CC];
__device__ __nv_bfloat16 g_xl[(size_t)M_TOK * CC];
__device__ __nv_bfloat16 g_qkwh[(size_t)2 * CC * CC];
__device__ __nv_bfloat16 g_qkwl[(size_t)2 * CC * CC];
__device__ __nv_bfloat16 g_pwh[(size_t)CC * CC];
__device__ __nv_bfloat16 g_pwl[(size_t)CC * CC];
__device__ __nv_bfloat16 g_ah[(size_t)M_TOK * CC];
__device__ __nv_bfloat16 g_al[(size_t)M_TOK * CC];

// ---------------- packed f32x2 helpers (FFMA2) ------------------------------
__device__ __forceinline__ u64 dupf(float v) {
    u64 r; asm("mov.b64 %0, {%1, %1};" : "=l"(r) : "f"(v)); return r;
}
__device__ __forceinline__ void ffma2(u64& d, u64 a, u64 b) {
    asm("fma.rn.f32x2 %0, %1, %2, %0;" : "+l"(d) : "l"(a), "l"(b));
}
__device__ __forceinline__ float2 unpk(u64 v) {
    float2 f; asm("mov.b64 {%0, %1}, %2;" : "=f"(f.x), "=f"(f.y) : "l"(v)); return f;
}

// ---------------- warp-MMA helpers (HMMA path, no tcgen05) ------------------
__device__ __forceinline__ uint32_t smem_u32(const void* p) {
    uint32_t a;
    asm("{ .reg .u64 t; cvta.to.shared.u64 t, %1; cvt.u32.u64 %0, t; }" : "=r"(a) : "l"(p));
    return a;
}
__device__ __forceinline__ void ldm_x4(uint32_t* r, uint32_t addr) {
    asm volatile("ldmatrix.sync.aligned.m8n8.x4.shared.b16 {%0,%1,%2,%3}, [%4];"
        : "=r"(r[0]), "=r"(r[1]), "=r"(r[2]), "=r"(r[3]) : "r"(addr));
}
__device__ __forceinline__ void mma_bf16(float* c, const uint32_t* a, const uint32_t* b) {
    asm volatile("mma.sync.aligned.m16n8k16.row.col.f32.bf16.bf16.f32 "
        "{%0,%1,%2,%3}, {%4,%5,%6,%7}, {%8,%9}, {%0,%1,%2,%3};"
        : "+f"(c[0]), "+f"(c[1]), "+f"(c[2]), "+f"(c[3])
        : "r"(a[0]), "r"(a[1]), "r"(a[2]), "r"(a[3]), "r"(b[0]), "r"(b[1]));
}

// ---------------------------------------------------------------------------
// split fp32 -> bf16 hi + bf16 lo (residual). n4 = count of float4 groups.
// ---------------------------------------------------------------------------
__global__ __launch_bounds__(256) void split_kernel(
    const float* __restrict__ src, __nv_bfloat16* __restrict__ hi,
    __nv_bfloat16* __restrict__ lo, int n4)
{
    int i = blockIdx.x * 256 + threadIdx.x;
    if (i >= n4) return;
    float4 v = ((const float4*)src)[i];
    __nv_bfloat16 h0 = __float2bfloat16(v.x);
    __nv_bfloat16 h1 = __float2bfloat16(v.y);
    __nv_bfloat16 h2 = __float2bfloat16(v.z);
    __nv_bfloat16 h3 = __float2bfloat16(v.w);
    __nv_bfloat16 l0 = __float2bfloat16(v.x - __bfloat162float(h0));
    __nv_bfloat16 l1 = __float2bfloat16(v.y - __bfloat162float(h1));
    __nv_bfloat16 l2 = __float2bfloat16(v.z - __bfloat162float(h2));
    __nv_bfloat16 l3 = __float2bfloat16(v.w - __bfloat162float(h3));
    __nv_bfloat162* hp = (__nv_bfloat162*)hi;
    __nv_bfloat162* lp = (__nv_bfloat162*)lo;
    hp[2 * i]     = __nv_bfloat162(h0, h1);
    hp[2 * i + 1] = __nv_bfloat162(h2, h3);
    lp[2 * i]     = __nv_bfloat162(l0, l1);
    lp[2 * i + 1] = __nv_bfloat162(l2, l3);
}

// ---------------------------------------------------------------------------
// HMMA GEMM with bf16 3-term split:
//   C[M,Nc] = (Ah+Al)[M,K] @ (Bh+Bl)[Nc,K]^T  (+ bias)
// 128x128 CTA tile, 8 warps (2x4), warp tile 64x32, BK=32, double-buffered.
// smem tiles padded to 40 elements/row (80B) -> conflict-free ldmatrix.
// ---------------------------------------------------------------------------
#define LDT 40
#define TILE_ELE (128 * LDT)        // elements per tile
#define TILE_BYT (TILE_ELE * 2)     // 10240 bytes
#define STAGE_ELE (4 * TILE_ELE)
#define GEMM_SMEM (2 * STAGE_ELE * 2)   // 81920 bytes

template <bool BIAS>
__global__ __launch_bounds__(256, 1) void gemm3h_kernel(
    const __nv_bfloat16* __restrict__ Ah, const __nv_bfloat16* __restrict__ Al,
    const __nv_bfloat16* __restrict__ Bh, const __nv_bfloat16* __restrict__ Bl,
    const float* __restrict__ bias, float* __restrict__ C,
    int M, int Nc, int K)
{
    extern __shared__ __nv_bfloat16 smem[];
    const int t = threadIdx.x;
    const int lane = t & 31, wid = t >> 5;
    const int warpM = wid & 1;          // 0..1 -> 64-row half
    const int warpN = wid >> 1;         // 0..3 -> 32-col group
    const int mbase = blockIdx.y * 128;
    const int nbase = blockIdx.x * 128;

    const __nv_bfloat16* base[4] = {
        Ah + (size_t)mbase * K, Al + (size_t)mbase * K,
        Bh + (size_t)nbase * K, Bl + (size_t)nbase * K };

    // loader mapping: per tile 512 uint4; thread does idx=t and t+256
    const int lr0 = t >> 2;             // rows 0..63
    const int lc4 = t & 3;              // 16B chunk

    float acc[4][4][4];
#pragma unroll
    for (int m = 0; m < 4; m++)
#pragma unroll
        for (int n = 0; n < 4; n++)
#pragma unroll
            for (int j = 0; j < 4; j++) acc[m][n][j] = 0.f;

    uint4 rg[4][2];

    auto g_load = [&](int kt) {
#pragma unroll
        for (int tl = 0; tl < 4; tl++) {
            rg[tl][0] = *(const uint4*)(base[tl] + (size_t)lr0 * K + kt + lc4 * 8);
            rg[tl][1] = *(const uint4*)(base[tl] + (size_t)(lr0 + 64) * K + kt + lc4 * 8);
        }
    };
    auto s_store = [&](int s) {
        __nv_bfloat16* sb = smem + s * STAGE_ELE;
#pragma unroll
        for (int tl = 0; tl < 4; tl++) {
            *(uint4*)(sb + tl * TILE_ELE + lr0 * LDT + lc4 * 8) = rg[tl][0];
            *(uint4*)(sb + tl * TILE_ELE + (lr0 + 64) * LDT + lc4 * 8) = rg[tl][1];
        }
    };

    // per-thread ldmatrix byte offsets (within a tile)
    const int a_row = warpM * 64 + (lane & 15);         // + m*16
    const int a_colh = (lane >> 4) << 3;                 // 0 or 8, + kk
    const int b_row = warpN * 32 + ((lane >> 4) << 3) + (lane & 7);  // + p*16
    const int b_colh = ((lane >> 3) & 1) << 3;           // 0 or 8, + kk

    const int NIT = K / 32;

    g_load(0);
    s_store(0);
    __syncthreads();

    for (int it = 0; it < NIT; it++) {
        int cur = it & 1;
        if (it + 1 < NIT) g_load((it + 1) * 32);

        uint32_t sa = smem_u32(smem + cur * STAGE_ELE);
#pragma unroll
        for (int kk = 0; kk < 32; kk += 16) {
            uint32_t ah[4][4], al[4][4];
#pragma unroll
            for (int m = 0; m < 4; m++) {
                uint32_t off = ((a_row + m * 16) * LDT + kk + a_colh) * 2;
                ldm_x4(ah[m], sa + off);
                ldm_x4(al[m], sa + TILE_BYT + off);
            }
            uint32_t bh[2][4], bl[2][4];
#pragma unroll
            for (int p = 0; p < 2; p++) {
                uint32_t off = ((b_row + p * 16) * LDT + kk + b_colh) * 2;
                ldm_x4(bh[p], sa + 2 * TILE_BYT + off);
                ldm_x4(bl[p], sa + 3 * TILE_BYT + off);
            }
#pragma unroll
            for (int m = 0; m < 4; m++) {
#pragma unroll
                for (int n = 0; n < 4; n++) {
                    const uint32_t* bhf = &bh[n >> 1][(n & 1) * 2];
                    const uint32_t* blf = &bl[n >> 1][(n & 1) * 2];
                    mma_bf16(acc[m][n], ah[m], bhf);
                    mma_bf16(acc[m][n], ah[m], blf);
                    mma_bf16(acc[m][n], al[m], bhf);
                }
            }
        }

        if (it + 1 < NIT) {
            __syncthreads();
            s_store(cur ^ 1);
            __syncthreads();
        }
    }

    // epilogue
    const int g = lane >> 2;
    const int cp = (lane & 3) * 2;
#pragma unroll
    for (int m = 0; m < 4; m++) {
        int row0 = mbase + warpM * 64 + m * 16 + g;
#pragma unroll
        for (int n = 0; n < 4; n++) {
            int col = nbase + warpN * 32 + n * 8 + cp;
            float b0 = 0.f, b1 = 0.f;
            if (BIAS) { b0 = bias[col]; b1 = bias[col + 1]; }
            float2 v0 = make_float2(acc[m][n][0] + b0, acc[m][n][1] + b1);
            float2 v1 = make_float2(acc[m][n][2] + b0, acc[m][n][3] + b1);
            *(float2*)(C + (size_t)row0 * Nc + col) = v0;
            *(float2*)(C + (size_t)(row0 + 8) * Nc + col) = v1;
        }
    }
}

// ---------------------------------------------------------------------------
// In-place L2 normalize every contiguous 64-float group of g_qk.
// ---------------------------------------------------------------------------
__global__ __launch_bounds__(256) void l2norm_kernel(float* __restrict__ g)
{
    int gidx = blockIdx.x * 8 + (threadIdx.x >> 5);
    int lane = threadIdx.x & 31;
    float* p = g + (size_t)gidx * 64;
    float v0 = p[lane];
    float v1 = p[lane + 32];
    float s = v0 * v0 + v1 * v1;
#pragma unroll
    for (int off = 16; off; off >>= 1) s += __shfl_xor_sync(0xffffffffu, s, off);
    float inv = 1.0f / fmaxf(sqrtf(s), 1e-12f);
    p[lane] = v0 * inv;
    p[lane + 32] = v1 * inv;
}

// ---------------------------------------------------------------------------
// genw: fold subsampled low-rank weights into per-(b,h) 64x64 AE/AR
// ---------------------------------------------------------------------------
__global__ __launch_bounds__(256) void genw_kernel(
    const float* __restrict__ x, const float* __restrict__ we,
    const float* __restrict__ wr, const float* __restrict__ cw_w)
{
    int bh = blockIdx.x;
    int b = bh >> 4, h = bh & 15;
    __shared__ int   idx_s[RR];
    __shared__ float web[HD][LR], wrb[HD][LR];
    int t = threadIdx.x;

    if (t < RR) idx_s[t] = (int)((double)t * (double)(NN - 1) / (double)(RR - 1));
    __syncthreads();

    for (int it = t; it < HD * LR; it += 256) {
        int d = it / LR, e = it % LR;
        float se = 0.f, sr = 0.f;
        for (int r = 0; r < RR; r++) {
            float xv = x[((size_t)b * NN + idx_s[r]) * CC + h * HD + d];
            se += xv * we[((size_t)h * RR + r) * LR + e];
            sr += xv * wr[((size_t)h * RR + r) * LR + e];
        }
        web[d][e] = se;
        wrb[d][e] = sr;
    }
    __syncthreads();

    for (int it = t; it < HD * HD; it += 256) {
        int d = it >> 6, o = it & 63;
        float ae = 0.f, ar = 0.f;
#pragma unroll
        for (int e = 0; e < LR; e++) {
            ae += web[d][e] * cw_w[o * (2 * LR) + e];
            ar += wrb[d][e] * cw_w[o * (2 * LR) + LR + e];
        }
        size_t base = ((size_t)bh * HD + d) * HD + o;
        g_AE[base] = ae;
        g_AR[base] = ar;
    }
}

// ---------------------------------------------------------------------------
// score: attn = q@AE + k@AR + cw_b  (FFMA2, smem-staged)
// ---------------------------------------------------------------------------
__global__ __launch_bounds__(256) void score_kernel(const float* __restrict__ cw_b)
{
    extern __shared__ float smf[];
    float* AEs = smf;
    float* ARs = smf + 4096;
    float* Qt  = smf + 8192;
    float* Kt  = smf + 12288;

    const int nt = blockIdx.x;
    const int bh = blockIdx.y;
    const int b = bh >> 4, h = bh & 15;
    const int t = threadIdx.x;

    const float4* gAE = (const float4*)(g_AE + (size_t)bh * HD * HD);
    const float4* gAR = (const float4*)(g_AR + (size_t)bh * HD * HD);
#pragma unroll
    for (int i = t; i < 1024; i += 256) {
        ((float4*)AEs)[i] = gAE[i];
        ((float4*)ARs)[i] = gAR[i];
    }
#pragma unroll
    for (int i = t; i < 1024; i += 256) {
        int tt = i & 63;
        int d4 = (i >> 6) << 2;
        const float* qrow = g_qk + ((size_t)(b * NN + nt * 64 + tt)) * (2 * CC) + h * HD;
        float4 qv = *(const float4*)(qrow + d4);
        float4 kv = *(const float4*)(qrow + CC + d4);
        Qt[(d4 + 0) * 64 + tt] = qv.x; Qt[(d4 + 1) * 64 + tt] = qv.y;
        Qt[(d4 + 2) * 64 + tt] = qv.z; Qt[(d4 + 3) * 64 + tt] = qv.w;
        Kt[(d4 + 0) * 64 + tt] = kv.x; Kt[(d4 + 1) * 64 + tt] = kv.y;
        Kt[(d4 + 2) * 64 + tt] = kv.z; Kt[(d4 + 3) * 64 + tt] = kv.w;
    }
    __syncthreads();

    const int tg = t >> 3;
    const int o8 = (t & 7) * 8;
    const int t0 = tg * 2, t1 = t0 + 1;

    u64 acc0[4] = {0ull, 0ull, 0ull, 0ull};
    u64 acc1[4] = {0ull, 0ull, 0ull, 0ull};

#pragma unroll 8
    for (int d = 0; d < HD; d++) {
        u64 q0 = dupf(Qt[d * 64 + t0]);
        u64 q1 = dupf(Qt[d * 64 + t1]);
        u64 k0 = dupf(Kt[d * 64 + t0]);
        u64 k1 = dupf(Kt[d * 64 + t1]);
        ulonglong2 e01 = *(const ulonglong2*)&AEs[d * 64 + o8];
        ulonglong2 e23 = *(const ulonglong2*)&AEs[d * 64 + o8 + 4];
        ulonglong2 r01 = *(const ulonglong2*)&ARs[d * 64 + o8];
        ulonglong2 r23 = *(const ulonglong2*)&ARs[d * 64 + o8 + 4];
        ffma2(acc0[0], q0, e01.x); ffma2(acc0[1], q0, e01.y);
        ffma2(acc0[2], q0, e23.x); ffma2(acc0[3], q0, e23.y);
        ffma2(acc1[0], q1, e01.x); ffma2(acc1[1], q1, e01.y);
        ffma2(acc1[2], q1, e23.x); ffma2(acc1[3], q1, e23.y);
        ffma2(acc0[0], k0, r01.x); ffma2(acc0[1], k0, r01.y);
        ffma2(acc0[2], k0, r23.x); ffma2(acc0[3], k0, r23.y);
        ffma2(acc1[0], k1, r01.x); ffma2(acc1[1], k1, r01.y);
        ffma2(acc1[2], k1, r23.x); ffma2(acc1[3], k1, r23.y);
    }

    float cb0 = cw_b[o8 + 0], cb1 = cw_b[o8 + 1], cb2 = cw_b[o8 + 2], cb3 = cw_b[o8 + 3];
    float cb4 = cw_b[o8 + 4], cb5 = cw_b[o8 + 5], cb6 = cw_b[o8 + 6], cb7 = cw_b[o8 + 7];

    int nbase = nt * 64;
    {
        float2 p0 = unpk(acc0[0]), p1 = unpk(acc0[1]), p2 = unpk(acc0[2]), p3 = unpk(acc0[3]);
        float* out = g_attn + ((size_t)(b * NN + nbase + t0)) * CC + h * HD + o8;
        *(float4*)out = make_float4(p0.x + cb0, p0.y + cb1, p1.x + cb2, p1.y + cb3);
        *(float4*)(out + 4) = make_float4(p2.x + cb4, p2.y + cb5, p3.x + cb6, p3.y + cb7);
    }
    {
        float2 p0 = unpk(acc1[0]), p1 = unpk(acc1[1]), p2 = unpk(acc1[2]), p3 = unpk(acc1[3]);
        float* out = g_attn + ((size_t)(b * NN + nbase + t1)) * CC + h * HD + o8;
        *(float4*)out = make_float4(p0.x + cb0, p0.y + cb1, p1.x + cb2, p1.y + cb3);
        *(float4*)(out + 4) = make_float4(p2.x + cb4, p2.y + cb5, p3.x + cb6, p3.y + cb7);
    }
}

// ---------------------------------------------------------------------------
extern "C" void kernel_launch(void* const* d_in, const int* in_sizes, int n_in,
                              void* d_out, int out_size)
{
    const float* x      = (const float*)d_in[0];
    const float* qk_w   = (const float*)d_in[1];
    const float* proj_w = (const float*)d_in[2];
    const float* proj_b = (const float*)d_in[3];
    const float* we     = (const float*)d_in[4];
    const float* wr     = (const float*)d_in[5];
    const float* cw_w   = (const float*)d_in[6];
    const float* cw_b   = (const float*)d_in[7];
    float* out = (float*)d_out;

    void *p_qk, *p_attn, *p_xh, *p_xl, *p_qkwh, *p_qkwl, *p_pwh, *p_pwl, *p_ah, *p_al;
    cudaGetSymbolAddress(&p_qk, g_qk);
    cudaGetSymbolAddress(&p_attn, g_attn);
    cudaGetSymbolAddress(&p_xh, g_xh);
    cudaGetSymbolAddress(&p_xl, g_xl);
    cudaGetSymbolAddress(&p_qkwh, g_qkwh);
    cudaGetSymbolAddress(&p_qkwl, g_qkwl);
    cudaGetSymbolAddress(&p_pwh, g_pwh);
    cudaGetSymbolAddress(&p_pwl, g_pwl);
    cudaGetSymbolAddress(&p_ah, g_ah);
    cudaGetSymbolAddress(&p_al, g_al);
    float* qk   = (float*)p_qk;
    float* attn = (float*)p_attn;

    cudaFuncSetAttribute(score_kernel, cudaFuncAttributeMaxDynamicSharedMemorySize, 65536);
    cudaFuncSetAttribute(gemm3h_kernel<false>, cudaFuncAttributeMaxDynamicSharedMemorySize, GEMM_SMEM);
    cudaFuncSetAttribute(gemm3h_kernel<true>,  cudaFuncAttributeMaxDynamicSharedMemorySize, GEMM_SMEM);

    // 0) split inputs to bf16 hi/lo
    split_kernel<<<(M_TOK * CC / 4) / 256, 256>>>(x, (__nv_bfloat16*)p_xh, (__nv_bfloat16*)p_xl, M_TOK * CC / 4);
    split_kernel<<<(2 * CC * CC / 4) / 256, 256>>>(qk_w, (__nv_bfloat16*)p_qkwh, (__nv_bfloat16*)p_qkwl, 2 * CC * CC / 4);
    split_kernel<<<(CC * CC / 4) / 256, 256>>>(proj_w, (__nv_bfloat16*)p_pwh, (__nv_bfloat16*)p_pwl, CC * CC / 4);

    // 1) qk = x @ qk_w^T  (HMMA, bf16 x3)
    gemm3h_kernel<false><<<dim3(2 * CC / 128, M_TOK / 128), 256, GEMM_SMEM>>>(
        (const __nv_bfloat16*)p_xh, (const __nv_bfloat16*)p_xl,
        (const __nv_bfloat16*)p_qkwh, (const __nv_bfloat16*)p_qkwl,
        nullptr, qk, M_TOK, 2 * CC, CC);

    // 2) per-64 L2 normalize in place
    l2norm_kernel<<<(M_TOK * 2 * CC / 64) / 8, 256>>>(qk);

    // 3) AE/AR
    genw_kernel<<<BB * HH, 256>>>(x, we, wr, cw_w);

    // 4) attn = q@AE + k@AR + cw_b
    score_kernel<<<dim3(NN / 64, BB * HH), 256, 65536>>>(cw_b);

    // 5) split attn to bf16 hi/lo
    split_kernel<<<(M_TOK * CC / 4) / 256, 256>>>(attn, (__nv_bfloat16*)p_ah, (__nv_bfloat16*)p_al, M_TOK * CC / 4);

    // 6) out = attn @ proj_w^T + proj_b  (HMMA, bf16 x3)
    gemm3h_kernel<true><<<dim3(CC / 128, M_TOK / 128), 256, GEMM_SMEM>>>(
        (const __nv_bfloat16*)p_ah, (const __nv_bfloat16*)p_al,
        (const __nv_bfloat16*)p_pwh, (const __nv_bfloat16*)p_pwl,
        proj_b, out, M_TOK, CC, CC);
}

// round 9
// speedup vs baseline: 2.3705x; 1.0620x over previous
#include <cuda_runtime.h>
#include <cuda_bf16.h>
#include <cstdint>
#include <stdint.h>
#include <math.h>

// Problem constants (fixed by the dataset)
#define BB 4
#define NN 2048
#define CC 1024
#define HH 16
#define HD 64
#define LR 20
#define RR 200
#define M_TOK (BB * NN)   // 8192 token rows

typedef unsigned long long u64;

// ---------------- scratch (__device__ globals; no allocs allowed) -----------
__device__ float g_qk[(size_t)M_TOK * 2 * CC];   // [8192][2048] q|k fp32

__device__ __nv_bfloat16 g_xh[(size_t)M_TOK * CC];
__device__ __nv_bfloat16 g_xl[(size_t)M_TOK * CC];
__device__ __nv_bfloat16 g_qkwh[(size_t)2 * CC * CC];
__device__ __nv_bfloat16 g_qkwl[(size_t)2 * CC * CC];
__device__ __nv_bfloat16 g_pwh[(size_t)CC * CC];
__device__ __nv_bfloat16 g_pwl[(size_t)CC * CC];
__device__ __nv_bfloat16 g_ah[(size_t)M_TOK * CC];   // attn hi (split at source)
__device__ __nv_bfloat16 g_al[(size_t)M_TOK * CC];   // attn lo

// normalized q|k per head, [bh][n][128] (0-63 = q, 64-127 = k), bf16 hi/lo
__device__ __nv_bfloat16 g_qnh[(size_t)BB * HH * NN * 128];
__device__ __nv_bfloat16 g_qnl[(size_t)BB * HH * NN * 128];
// combined per-(b,h) weights [bh][o(64)][d(128)]: d<64 -> AE[d][o], d>=64 -> AR[d-64][o]
__device__ __nv_bfloat16 g_bwh[(size_t)BB * HH * HD * 128];
__device__ __nv_bfloat16 g_bwl[(size_t)BB * HH * HD * 128];

// ---------------- helpers ----------------------------------------------------
__device__ __forceinline__ uint32_t smem_u32(const void* p) {
    uint32_t a;
    asm("{ .reg .u64 t; cvta.to.shared.u64 t, %1; cvt.u32.u64 %0, t; }" : "=r"(a) : "l"(p));
    return a;
}
__device__ __forceinline__ void ldm_x4(uint32_t* r, uint32_t addr) {
    asm volatile("ldmatrix.sync.aligned.m8n8.x4.shared.b16 {%0,%1,%2,%3}, [%4];"
        : "=r"(r[0]), "=r"(r[1]), "=r"(r[2]), "=r"(r[3]) : "r"(addr));
}
__device__ __forceinline__ void mma_bf16(float* c, const uint32_t* a, const uint32_t* b) {
    asm volatile("mma.sync.aligned.m16n8k16.row.col.f32.bf16.bf16.f32 "
        "{%0,%1,%2,%3}, {%4,%5,%6,%7}, {%8,%9}, {%0,%1,%2,%3};"
        : "+f"(c[0]), "+f"(c[1]), "+f"(c[2]), "+f"(c[3])
        : "r"(a[0]), "r"(a[1]), "r"(a[2]), "r"(a[3]), "r"(b[0]), "r"(b[1]));
}
__device__ __forceinline__ void cpasync16(uint32_t dst, const void* src) {
    asm volatile("cp.async.cg.shared.global [%0], [%1], 16;" :: "r"(dst), "l"(src));
}
// split a float pair into bf16 hi/lo pairs and store
__device__ __forceinline__ void split_store2(float a, float b,
                                             __nv_bfloat16* hp, __nv_bfloat16* lp) {
    __nv_bfloat16 h0 = __float2bfloat16(a);
    __nv_bfloat16 h1 = __float2bfloat16(b);
    *(__nv_bfloat162*)hp = __nv_bfloat162(h0, h1);
    *(__nv_bfloat162*)lp = __nv_bfloat162(
        __float2bfloat16(a - __bfloat162float(h0)),
        __float2bfloat16(b - __bfloat162float(h1)));
}

// ---------------------------------------------------------------------------
// split fp32 -> bf16 hi + bf16 lo (residual). n4 = count of float4 groups.
// ---------------------------------------------------------------------------
__global__ __launch_bounds__(256) void split_kernel(
    const float* __restrict__ src, __nv_bfloat16* __restrict__ hi,
    __nv_bfloat16* __restrict__ lo, int n4)
{
    int i = blockIdx.x * 256 + threadIdx.x;
    if (i >= n4) return;
    float4 v = ((const float4*)src)[i];
    __nv_bfloat16 h0 = __float2bfloat16(v.x);
    __nv_bfloat16 h1 = __float2bfloat16(v.y);
    __nv_bfloat16 h2 = __float2bfloat16(v.z);
    __nv_bfloat16 h3 = __float2bfloat16(v.w);
    __nv_bfloat162* hp = (__nv_bfloat162*)hi;
    __nv_bfloat162* lp = (__nv_bfloat162*)lo;
    hp[2 * i]     = __nv_bfloat162(h0, h1);
    hp[2 * i + 1] = __nv_bfloat162(h2, h3);
    lp[2 * i]     = __nv_bfloat162(__float2bfloat16(v.x - __bfloat162float(h0)),
                                   __float2bfloat16(v.y - __bfloat162float(h1)));
    lp[2 * i + 1] = __nv_bfloat162(__float2bfloat16(v.z - __bfloat162float(h2)),
                                   __float2bfloat16(v.w - __bfloat162float(h3)));
}

// ---------------------------------------------------------------------------
// HMMA GEMM with bf16 3-term split + cp.async double buffering:
//   C[M,Nc] = (Ah+Al)[M,K] @ (Bh+Bl)[Nc,K]^T  (+ bias)
// 128x128 CTA tile, 8 warps (2x4), warp tile 64x32, BK=32.
// ---------------------------------------------------------------------------
#define LDT 40
#define TILE_ELE (128 * LDT)
#define TILE_BYT (TILE_ELE * 2)
#define STAGE_BYT (4 * TILE_BYT)
#define GEMM_SMEM (2 * STAGE_BYT)    // 163840? no: 2*4*10240 = 81920 bytes

template <bool BIAS>
__global__ __launch_bounds__(256, 1) void gemm3h_kernel(
    const __nv_bfloat16* __restrict__ Ah, const __nv_bfloat16* __restrict__ Al,
    const __nv_bfloat16* __restrict__ Bh, const __nv_bfloat16* __restrict__ Bl,
    const float* __restrict__ bias, float* __restrict__ C,
    int M, int Nc, int K)
{
    extern __shared__ __nv_bfloat16 smem[];
    const int t = threadIdx.x;
    const int lane = t & 31, wid = t >> 5;
    const int warpM = wid & 1;
    const int warpN = wid >> 1;
    const int mbase = blockIdx.y * 128;
    const int nbase = blockIdx.x * 128;
    const uint32_t smb = smem_u32(smem);

    const __nv_bfloat16* base[4] = {
        Ah + (size_t)mbase * K, Al + (size_t)mbase * K,
        Bh + (size_t)nbase * K, Bl + (size_t)nbase * K };

    const int lr0 = t >> 2;             // 0..63
    const int lc4 = t & 3;              // 16B chunk within 64B row

    float acc[4][4][4];
#pragma unroll
    for (int m = 0; m < 4; m++)
#pragma unroll
        for (int n = 0; n < 4; n++)
#pragma unroll
            for (int j = 0; j < 4; j++) acc[m][n][j] = 0.f;

    auto issue_stage = [&](int s, int kt) {
        uint32_t sb = smb + s * STAGE_BYT;
#pragma unroll
        for (int tl = 0; tl < 4; tl++) {
            const __nv_bfloat16* gp = base[tl] + (size_t)lr0 * K + kt + lc4 * 8;
            uint32_t dp = sb + tl * TILE_BYT + (lr0 * LDT + lc4 * 8) * 2;
            cpasync16(dp, gp);
            cpasync16(dp + 64 * LDT * 2, gp + (size_t)64 * K);
        }
        asm volatile("cp.async.commit_group;");
    };

    const int a_row = warpM * 64 + (lane & 15);
    const int a_colh = (lane >> 4) << 3;
    const int b_row = warpN * 32 + ((lane >> 4) << 3) + (lane & 7);
    const int b_colh = ((lane >> 3) & 1) << 3;

    const int NIT = K / 32;

    issue_stage(0, 0);

    for (int it = 0; it < NIT; it++) {
        int cur = it & 1;
        if (it + 1 < NIT) {
            issue_stage(cur ^ 1, (it + 1) * 32);
            asm volatile("cp.async.wait_group 1;");
        } else {
            asm volatile("cp.async.wait_group 0;");
        }
        __syncthreads();

        uint32_t sa = smb + cur * STAGE_BYT;
#pragma unroll
        for (int kk = 0; kk < 32; kk += 16) {
            uint32_t ah[4][4], al[4][4];
#pragma unroll
            for (int m = 0; m < 4; m++) {
                uint32_t off = ((a_row + m * 16) * LDT + kk + a_colh) * 2;
                ldm_x4(ah[m], sa + off);
                ldm_x4(al[m], sa + TILE_BYT + off);
            }
            uint32_t bh[2][4], bl[2][4];
#pragma unroll
            for (int p = 0; p < 2; p++) {
                uint32_t off = ((b_row + p * 16) * LDT + kk + b_colh) * 2;
                ldm_x4(bh[p], sa + 2 * TILE_BYT + off);
                ldm_x4(bl[p], sa + 3 * TILE_BYT + off);
            }
#pragma unroll
            for (int m = 0; m < 4; m++) {
#pragma unroll
                for (int n = 0; n < 4; n++) {
                    const uint32_t* bhf = &bh[n >> 1][(n & 1) * 2];
                    const uint32_t* blf = &bl[n >> 1][(n & 1) * 2];
                    mma_bf16(acc[m][n], ah[m], bhf);
                    mma_bf16(acc[m][n], ah[m], blf);
                    mma_bf16(acc[m][n], al[m], bhf);
                }
            }
        }
        __syncthreads();
    }

    // epilogue
    const int g = lane >> 2;
    const int cp = (lane & 3) * 2;
#pragma unroll
    for (int m = 0; m < 4; m++) {
        int row0 = mbase + warpM * 64 + m * 16 + g;
#pragma unroll
        for (int n = 0; n < 4; n++) {
            int col = nbase + warpN * 32 + n * 8 + cp;
            float b0 = 0.f, b1 = 0.f;
            if (BIAS) { b0 = bias[col]; b1 = bias[col + 1]; }
            float2 v0 = make_float2(acc[m][n][0] + b0, acc[m][n][1] + b1);
            float2 v1 = make_float2(acc[m][n][2] + b0, acc[m][n][3] + b1);
            *(float2*)(C + (size_t)row0 * Nc + col) = v0;
            *(float2*)(C + (size_t)(row0 + 8) * Nc + col) = v1;
        }
    }
}

// ---------------------------------------------------------------------------
// l2norm v2: normalize q/k per 64-group and emit bf16 hi/lo in per-head layout
// g_qn*[bh][n][0..63]=q_n, [64..127]=k_n.  One warp per (token, head).
// ---------------------------------------------------------------------------
__global__ __launch_bounds__(256) void l2norm2_kernel(const float* __restrict__ qk)
{
    int w = blockIdx.x * 8 + (threadIdx.x >> 5);   // 0..131071
    int lane = threadIdx.x & 31;
    int tok = w >> 4;
    int h = w & 15;
    int b = tok >> 11;
    int n = tok & 2047;

    const float* qp = qk + (size_t)tok * (2 * CC) + h * HD;
    const float* kp = qp + CC;
    float q0 = qp[lane], q1 = qp[lane + 32];
    float k0 = kp[lane], k1 = kp[lane + 32];
    float sq = q0 * q0 + q1 * q1;
    float sk = k0 * k0 + k1 * k1;
#pragma unroll
    for (int off = 16; off; off >>= 1) {
        sq += __shfl_xor_sync(0xffffffffu, sq, off);
        sk += __shfl_xor_sync(0xffffffffu, sk, off);
    }
    float iq = 1.0f / fmaxf(sqrtf(sq), 1e-12f);
    float ik = 1.0f / fmaxf(sqrtf(sk), 1e-12f);
    q0 *= iq; q1 *= iq; k0 *= ik; k1 *= ik;

    size_t base = ((size_t)(b * HH + h) * NN + n) * 128;
    __nv_bfloat16 h0 = __float2bfloat16(q0);
    __nv_bfloat16 h1 = __float2bfloat16(q1);
    __nv_bfloat16 h2 = __float2bfloat16(k0);
    __nv_bfloat16 h3 = __float2bfloat16(k1);
    g_qnh[base + lane]       = h0;
    g_qnh[base + lane + 32]  = h1;
    g_qnh[base + 64 + lane]  = h2;
    g_qnh[base + 96 + lane]  = h3;
    g_qnl[base + lane]       = __float2bfloat16(q0 - __bfloat162float(h0));
    g_qnl[base + lane + 32]  = __float2bfloat16(q1 - __bfloat162float(h1));
    g_qnl[base + 64 + lane]  = __float2bfloat16(k0 - __bfloat162float(h2));
    g_qnl[base + 96 + lane]  = __float2bfloat16(k1 - __bfloat162float(h3));
}

// ---------------------------------------------------------------------------
// genw v2: per (b,h) fold subsampled low-rank weights with cw_w, emit combined
// weight matrix BW[o][d] (d<64: AE[d][o], d>=64: AR[d-64][o]) as bf16 hi/lo.
// ---------------------------------------------------------------------------
__global__ __launch_bounds__(256) void genw_kernel(
    const float* __restrict__ x, const float* __restrict__ we,
    const float* __restrict__ wr, const float* __restrict__ cw_w)
{
    int bh = blockIdx.x;
    int b = bh >> 4, h = bh & 15;
    __shared__ int   idx_s[RR];
    __shared__ float web[HD][LR], wrb[HD][LR];
    int t = threadIdx.x;

    if (t < RR) idx_s[t] = (int)((double)t * (double)(NN - 1) / (double)(RR - 1));
    __syncthreads();

    for (int it = t; it < HD * LR; it += 256) {
        int d = it / LR, e = it % LR;
        float se = 0.f, sr = 0.f;
        for (int r = 0; r < RR; r++) {
            float xv = x[((size_t)b * NN + idx_s[r]) * CC + h * HD + d];
            se += xv * we[((size_t)h * RR + r) * LR + e];
            sr += xv * wr[((size_t)h * RR + r) * LR + e];
        }
        web[d][e] = se;
        wrb[d][e] = sr;
    }
    __syncthreads();

    __nv_bfloat16* bwh = g_bwh + (size_t)bh * HD * 128;
    __nv_bfloat16* bwl = g_bwl + (size_t)bh * HD * 128;
    for (int it = t; it < HD * HD; it += 256) {
        int d = it >> 6, o = it & 63;
        float ae = 0.f, ar = 0.f;
#pragma unroll
        for (int e = 0; e < LR; e++) {
            ae += web[d][e] * cw_w[o * (2 * LR) + e];
            ar += wrb[d][e] * cw_w[o * (2 * LR) + LR + e];
        }
        __nv_bfloat16 ha = __float2bfloat16(ae);
        __nv_bfloat16 hr = __float2bfloat16(ar);
        bwh[o * 128 + d]      = ha;
        bwh[o * 128 + 64 + d] = hr;
        bwl[o * 128 + d]      = __float2bfloat16(ae - __bfloat162float(ha));
        bwl[o * 128 + 64 + d] = __float2bfloat16(ar - __bfloat162float(hr));
    }
}

// ---------------------------------------------------------------------------
// score via HMMA: per bh, attn_tile[256,64] = QK[256,128] @ BW[64,128]^T + cw_b
// 3-term bf16 split; output written directly as bf16 hi/lo (feeds GEMM2).
// 8 warps: warpM=wid>>1 (4 x 64 rows), warpN=wid&1 (2 x 32 cols).
// Dynamic smem: sAh 256x40 | sAl | sBh 64x40 | sBl  (51200 B)
// ---------------------------------------------------------------------------
#define SC_SMEM ((2 * 256 * LDT + 2 * 64 * LDT) * 2)

__global__ __launch_bounds__(256, 1) void score_mma_kernel(const float* __restrict__ cw_b)
{
    extern __shared__ __nv_bfloat16 ssm[];
    __nv_bfloat16* sAh = ssm;                      // 256*40
    __nv_bfloat16* sAl = ssm + 256 * LDT;
    __nv_bfloat16* sBh = ssm + 2 * 256 * LDT;      // 64*40
    __nv_bfloat16* sBl = ssm + 2 * 256 * LDT + 64 * LDT;

    const int t = threadIdx.x;
    const int lane = t & 31, wid = t >> 5;
    const int warpM = wid >> 1;
    const int warpN = wid & 1;
    const int tileM = blockIdx.x;      // 0..7 (256-token tiles)
    const int bh = blockIdx.y;
    const int b = bh >> 4, h = bh & 15;

    const __nv_bfloat16* Abh = g_qnh + ((size_t)bh * NN + tileM * 256) * 128;
    const __nv_bfloat16* Abl = g_qnl + ((size_t)bh * NN + tileM * 256) * 128;
    const __nv_bfloat16* Bbh = g_bwh + (size_t)bh * HD * 128;
    const __nv_bfloat16* Bbl = g_bwl + (size_t)bh * HD * 128;

    const uint32_t smb = smem_u32(ssm);
    const uint32_t offAl = 256 * LDT * 2;
    const uint32_t offBh = 2 * 256 * LDT * 2;
    const uint32_t offBl = offBh + 64 * LDT * 2;

    float acc[4][4][4];
#pragma unroll
    for (int m = 0; m < 4; m++)
#pragma unroll
        for (int n = 0; n < 4; n++)
#pragma unroll
            for (int j = 0; j < 4; j++) acc[m][n][j] = 0.f;

    const int a_row = warpM * 64 + (lane & 15);
    const int a_colh = (lane >> 4) << 3;
    const int b_row = warpN * 32 + ((lane >> 4) << 3) + (lane & 7);
    const int b_colh = ((lane >> 3) & 1) << 3;

    for (int ck = 0; ck < 4; ck++) {
        int kt = ck * 32;
        if (ck) __syncthreads();
        // A: 1024 x 16B per operand
#pragma unroll
        for (int j = 0; j < 4; j++) {
            int idx = t + j * 256;
            int row = idx >> 2, c = idx & 3;
            *(uint4*)(sAh + row * LDT + c * 8) = *(const uint4*)(Abh + (size_t)row * 128 + kt + c * 8);
            *(uint4*)(sAl + row * LDT + c * 8) = *(const uint4*)(Abl + (size_t)row * 128 + kt + c * 8);
        }
        // B: 256 x 16B per operand
        {
            int row = t >> 2, c = t & 3;
            if (row < 64) {
                *(uint4*)(sBh + row * LDT + c * 8) = *(const uint4*)(Bbh + (size_t)row * 128 + kt + c * 8);
                *(uint4*)(sBl + row * LDT + c * 8) = *(const uint4*)(Bbl + (size_t)row * 128 + kt + c * 8);
            }
        }
        __syncthreads();

#pragma unroll
        for (int kk = 0; kk < 32; kk += 16) {
            uint32_t ah[4][4], al[4][4];
#pragma unroll
            for (int m = 0; m < 4; m++) {
                uint32_t off = ((a_row + m * 16) * LDT + kk + a_colh) * 2;
                ldm_x4(ah[m], smb + off);
                ldm_x4(al[m], smb + offAl + off);
            }
            uint32_t bhf[2][4], blf[2][4];
#pragma unroll
            for (int p = 0; p < 2; p++) {
                uint32_t off = ((b_row + p * 16) * LDT + kk + b_colh) * 2;
                ldm_x4(bhf[p], smb + offBh + off);
                ldm_x4(blf[p], smb + offBl + off);
            }
#pragma unroll
            for (int m = 0; m < 4; m++) {
#pragma unroll
                for (int n = 0; n < 4; n++) {
                    const uint32_t* bh2 = &bhf[n >> 1][(n & 1) * 2];
                    const uint32_t* bl2 = &blf[n >> 1][(n & 1) * 2];
                    mma_bf16(acc[m][n], ah[m], bh2);
                    mma_bf16(acc[m][n], ah[m], bl2);
                    mma_bf16(acc[m][n], al[m], bh2);
                }
            }
        }
    }

    // epilogue: +cw_b, split to bf16 hi/lo, store into attn (g_ah/g_al)
    const int g = lane >> 2;
    const int cp = (lane & 3) * 2;
#pragma unroll
    for (int m = 0; m < 4; m++) {
        int n_tok = tileM * 256 + warpM * 64 + m * 16 + g;   // 0..2047
#pragma unroll
        for (int n = 0; n < 4; n++) {
            int col = warpN * 32 + n * 8 + cp;               // 0..63
            float b0 = cw_b[col], b1 = cw_b[col + 1];
            size_t r0 = ((size_t)(b * NN + n_tok)) * CC + h * HD + col;
            size_t r1 = ((size_t)(b * NN + n_tok + 8)) * CC + h * HD + col;
            split_store2(acc[m][n][0] + b0, acc[m][n][1] + b1, g_ah + r0, g_al + r0);
            split_store2(acc[m][n][2] + b0, acc[m][n][3] + b1, g_ah + r1, g_al + r1);
        }
    }
}

// ---------------------------------------------------------------------------
extern "C" void kernel_launch(void* const* d_in, const int* in_sizes, int n_in,
                              void* d_out, int out_size)
{
    const float* x      = (const float*)d_in[0];
    const float* qk_w   = (const float*)d_in[1];
    const float* proj_w = (const float*)d_in[2];
    const float* proj_b = (const float*)d_in[3];
    const float* we     = (const float*)d_in[4];
    const float* wr     = (const float*)d_in[5];
    const float* cw_w   = (const float*)d_in[6];
    const float* cw_b   = (const float*)d_in[7];
    float* out = (float*)d_out;

    void *p_qk, *p_xh, *p_xl, *p_qkwh, *p_qkwl, *p_pwh, *p_pwl, *p_ah, *p_al;
    cudaGetSymbolAddress(&p_qk, g_qk);
    cudaGetSymbolAddress(&p_xh, g_xh);
    cudaGetSymbolAddress(&p_xl, g_xl);
    cudaGetSymbolAddress(&p_qkwh, g_qkwh);
    cudaGetSymbolAddress(&p_qkwl, g_qkwl);
    cudaGetSymbolAddress(&p_pwh, g_pwh);
    cudaGetSymbolAddress(&p_pwl, g_pwl);
    cudaGetSymbolAddress(&p_ah, g_ah);
    cudaGetSymbolAddress(&p_al, g_al);
    float* qk = (float*)p_qk;

    cudaFuncSetAttribute(gemm3h_kernel<false>, cudaFuncAttributeMaxDynamicSharedMemorySize, GEMM_SMEM);
    cudaFuncSetAttribute(gemm3h_kernel<true>,  cudaFuncAttributeMaxDynamicSharedMemorySize, GEMM_SMEM);
    cudaFuncSetAttribute(score_mma_kernel, cudaFuncAttributeMaxDynamicSharedMemorySize, SC_SMEM);

    // 0) split inputs to bf16 hi/lo
    split_kernel<<<(M_TOK * CC / 4) / 256, 256>>>(x, (__nv_bfloat16*)p_xh, (__nv_bfloat16*)p_xl, M_TOK * CC / 4);
    split_kernel<<<(2 * CC * CC / 4) / 256, 256>>>(qk_w, (__nv_bfloat16*)p_qkwh, (__nv_bfloat16*)p_qkwl, 2 * CC * CC / 4);
    split_kernel<<<(CC * CC / 4) / 256, 256>>>(proj_w, (__nv_bfloat16*)p_pwh, (__nv_bfloat16*)p_pwl, CC * CC / 4);

    // 1) qk = x @ qk_w^T  (HMMA, bf16 x3, cp.async)
    gemm3h_kernel<false><<<dim3(2 * CC / 128, M_TOK / 128), 256, GEMM_SMEM>>>(
        (const __nv_bfloat16*)p_xh, (const __nv_bfloat16*)p_xl,
        (const __nv_bfloat16*)p_qkwh, (const __nv_bfloat16*)p_qkwl,
        nullptr, qk, M_TOK, 2 * CC, CC);

    // 2) normalize q/k -> bf16 hi/lo per-head layout
    l2norm2_kernel<<<(M_TOK * HH) / 8, 256>>>(qk);

    // 3) fold low-rank weights -> BW bf16 hi/lo
    genw_kernel<<<BB * HH, 256>>>(x, we, wr, cw_w);

    // 4) attn = [q|k] @ BW^T + cw_b  (HMMA), output split bf16 hi/lo
    score_mma_kernel<<<dim3(NN / 256, BB * HH), 256, SC_SMEM>>>(cw_b);

    // 5) out = attn @ proj_w^T + proj_b  (HMMA, bf16 x3, cp.async)
    gemm3h_kernel<true><<<dim3(CC / 128, M_TOK / 128), 256, GEMM_SMEM>>>(
        (const __nv_bfloat16*)p_ah, (const __nv_bfloat16*)p_al,
        (const __nv_bfloat16*)p_pwh, (const __nv_bfloat16*)p_pwl,
        proj_b, out, M_TOK, CC, CC);
}

// round 11
// speedup vs baseline: 2.7796x; 1.1725x over previous
#include <cuda_runtime.h>
#include <cuda_bf16.h>
#include <cstdint>
#include <stdint.h>
#include <math.h>

// Problem constants (fixed by the dataset)
#define BB 4
#define NN 2048
#define CC 1024
#define HH 16
#define HD 64
#define LR 20
#define RR 200
#define M_TOK (BB * NN)   // 8192 token rows

typedef unsigned long long u64;

// ---------------- scratch (__device__ globals; no allocs allowed) -----------
__device__ float g_qk[(size_t)M_TOK * 2 * CC];   // [8192][2048] q|k fp32

__device__ __nv_bfloat16 g_xh[(size_t)M_TOK * CC];
__device__ __nv_bfloat16 g_xl[(size_t)M_TOK * CC];
__device__ __nv_bfloat16 g_qkwh[(size_t)2 * CC * CC];
__device__ __nv_bfloat16 g_qkwl[(size_t)2 * CC * CC];
__device__ __nv_bfloat16 g_pwh[(size_t)CC * CC];
__device__ __nv_bfloat16 g_pwl[(size_t)CC * CC];
__device__ __nv_bfloat16 g_ah[(size_t)M_TOK * CC];   // attn hi (split at source)
__device__ __nv_bfloat16 g_al[(size_t)M_TOK * CC];   // attn lo

// normalized q|k per head, [bh][n][128] (0-63 = q, 64-127 = k), bf16 hi/lo
__device__ __nv_bfloat16 g_qnh[(size_t)BB * HH * NN * 128];
__device__ __nv_bfloat16 g_qnl[(size_t)BB * HH * NN * 128];
// combined per-(b,h) weights [bh][o(64)][d(128)]: d<64 -> AE[d][o], d>=64 -> AR[d-64][o]
__device__ __nv_bfloat16 g_bwh[(size_t)BB * HH * HD * 128];
__device__ __nv_bfloat16 g_bwl[(size_t)BB * HH * HD * 128];

// ---------------- helpers ----------------------------------------------------
__device__ __forceinline__ uint32_t smem_u32(const void* p) {
    uint32_t a;
    asm("{ .reg .u64 t; cvta.to.shared.u64 t, %1; cvt.u32.u64 %0, t; }" : "=r"(a) : "l"(p));
    return a;
}
__device__ __forceinline__ void ldm_x4(uint32_t* r, uint32_t addr) {
    asm volatile("ldmatrix.sync.aligned.m8n8.x4.shared.b16 {%0,%1,%2,%3}, [%4];"
        : "=r"(r[0]), "=r"(r[1]), "=r"(r[2]), "=r"(r[3]) : "r"(addr));
}
__device__ __forceinline__ void mma_bf16(float* c, const uint32_t* a, const uint32_t* b) {
    asm volatile("mma.sync.aligned.m16n8k16.row.col.f32.bf16.bf16.f32 "
        "{%0,%1,%2,%3}, {%4,%5,%6,%7}, {%8,%9}, {%0,%1,%2,%3};"
        : "+f"(c[0]), "+f"(c[1]), "+f"(c[2]), "+f"(c[3])
        : "r"(a[0]), "r"(a[1]), "r"(a[2]), "r"(a[3]), "r"(b[0]), "r"(b[1]));
}
__device__ __forceinline__ void cpasync16(uint32_t dst, const void* src) {
    asm volatile("cp.async.cg.shared.global [%0], [%1], 16;" :: "r"(dst), "l"(src));
}
// split a float pair into bf16 hi/lo pairs and store
__device__ __forceinline__ void split_store2(float a, float b,
                                             __nv_bfloat16* hp, __nv_bfloat16* lp) {
    __nv_bfloat16 h0 = __float2bfloat16(a);
    __nv_bfloat16 h1 = __float2bfloat16(b);
    *(__nv_bfloat162*)hp = __nv_bfloat162(h0, h1);
    *(__nv_bfloat162*)lp = __nv_bfloat162(
        __float2bfloat16(a - __bfloat162float(h0)),
        __float2bfloat16(b - __bfloat162float(h1)));
}

// ---------------------------------------------------------------------------
// split fp32 -> bf16 hi + bf16 lo (residual). n4 = count of float4 groups.
// ---------------------------------------------------------------------------
__global__ __launch_bounds__(256) void split_kernel(
    const float* __restrict__ src, __nv_bfloat16* __restrict__ hi,
    __nv_bfloat16* __restrict__ lo, int n4)
{
    int i = blockIdx.x * 256 + threadIdx.x;
    if (i >= n4) return;
    float4 v = ((const float4*)src)[i];
    __nv_bfloat16 h0 = __float2bfloat16(v.x);
    __nv_bfloat16 h1 = __float2bfloat16(v.y);
    __nv_bfloat16 h2 = __float2bfloat16(v.z);
    __nv_bfloat16 h3 = __float2bfloat16(v.w);
    __nv_bfloat162* hp = (__nv_bfloat162*)hi;
    __nv_bfloat162* lp = (__nv_bfloat162*)lo;
    hp[2 * i]     = __nv_bfloat162(h0, h1);
    hp[2 * i + 1] = __nv_bfloat162(h2, h3);
    lp[2 * i]     = __nv_bfloat162(__float2bfloat16(v.x - __bfloat162float(h0)),
                                   __float2bfloat16(v.y - __bfloat162float(h1)));
    lp[2 * i + 1] = __nv_bfloat162(__float2bfloat16(v.z - __bfloat162float(h2)),
                                   __float2bfloat16(v.w - __bfloat162float(h3)));
}

// ---------------------------------------------------------------------------
// HMMA GEMM with bf16 3-term split + cp.async double buffering:
//   C[M,Nc] = (Ah+Al)[M,K] @ (Bh+Bl)[Nc,K]^T  (+ bias)
// 128x128 CTA tile, 8 warps (2x4), warp tile 64x32, BK=32.
// __launch_bounds__(256, 2): 2 CTAs/SM so barrier bubbles overlap across CTAs.
// ---------------------------------------------------------------------------
#define LDT 40
#define TILE_ELE (128 * LDT)
#define TILE_BYT (TILE_ELE * 2)
#define STAGE_BYT (4 * TILE_BYT)
#define GEMM_SMEM (2 * STAGE_BYT)    // 81920 bytes

template <bool BIAS>
__global__ __launch_bounds__(256, 2) void gemm3h_kernel(
    const __nv_bfloat16* __restrict__ Ah, const __nv_bfloat16* __restrict__ Al,
    const __nv_bfloat16* __restrict__ Bh, const __nv_bfloat16* __restrict__ Bl,
    const float* __restrict__ bias, float* __restrict__ C,
    int M, int Nc, int K)
{
    extern __shared__ __nv_bfloat16 smem[];
    const int t = threadIdx.x;
    const int lane = t & 31, wid = t >> 5;
    const int warpM = wid & 1;
    const int warpN = wid >> 1;
    const int mbase = blockIdx.y * 128;
    const int nbase = blockIdx.x * 128;
    const uint32_t smb = smem_u32(smem);

    const __nv_bfloat16* base[4] = {
        Ah + (size_t)mbase * K, Al + (size_t)mbase * K,
        Bh + (size_t)nbase * K, Bl + (size_t)nbase * K };

    const int lr0 = t >> 2;             // 0..63
    const int lc4 = t & 3;              // 16B chunk within 64B row

    float acc[4][4][4];
#pragma unroll
    for (int m = 0; m < 4; m++)
#pragma unroll
        for (int n = 0; n < 4; n++)
#pragma unroll
            for (int j = 0; j < 4; j++) acc[m][n][j] = 0.f;

    auto issue_stage = [&](int s, int kt) {
        uint32_t sb = smb + s * STAGE_BYT;
#pragma unroll
        for (int tl = 0; tl < 4; tl++) {
            const __nv_bfloat16* gp = base[tl] + (size_t)lr0 * K + kt + lc4 * 8;
            uint32_t dp = sb + tl * TILE_BYT + (lr0 * LDT + lc4 * 8) * 2;
            cpasync16(dp, gp);
            cpasync16(dp + 64 * LDT * 2, gp + (size_t)64 * K);
        }
        asm volatile("cp.async.commit_group;");
    };

    const int a_row = warpM * 64 + (lane & 15);
    const int a_colh = (lane >> 4) << 3;
    const int b_row = warpN * 32 + ((lane >> 4) << 3) + (lane & 7);
    const int b_colh = ((lane >> 3) & 1) << 3;

    const int NIT = K / 32;

    issue_stage(0, 0);

    for (int it = 0; it < NIT; it++) {
        int cur = it & 1;
        if (it + 1 < NIT) {
            issue_stage(cur ^ 1, (it + 1) * 32);
            asm volatile("cp.async.wait_group 1;");
        } else {
            asm volatile("cp.async.wait_group 0;");
        }
        __syncthreads();

        uint32_t sa = smb + cur * STAGE_BYT;
#pragma unroll
        for (int kk = 0; kk < 32; kk += 16) {
            uint32_t ah[4][4], al[4][4];
#pragma unroll
            for (int m = 0; m < 4; m++) {
                uint32_t off = ((a_row + m * 16) * LDT + kk + a_colh) * 2;
                ldm_x4(ah[m], sa + off);
                ldm_x4(al[m], sa + TILE_BYT + off);
            }
            uint32_t bh[2][4], bl[2][4];
#pragma unroll
            for (int p = 0; p < 2; p++) {
                uint32_t off = ((b_row + p * 16) * LDT + kk + b_colh) * 2;
                ldm_x4(bh[p], sa + 2 * TILE_BYT + off);
                ldm_x4(bl[p], sa + 3 * TILE_BYT + off);
            }
#pragma unroll
            for (int m = 0; m < 4; m++) {
#pragma unroll
                for (int n = 0; n < 4; n++) {
                    const uint32_t* bhf = &bh[n >> 1][(n & 1) * 2];
                    const uint32_t* blf = &bl[n >> 1][(n & 1) * 2];
                    mma_bf16(acc[m][n], ah[m], bhf);
                    mma_bf16(acc[m][n], ah[m], blf);
                    mma_bf16(acc[m][n], al[m], bhf);
                }
            }
        }
        __syncthreads();
    }

    // epilogue
    const int g = lane >> 2;
    const int cp = (lane & 3) * 2;
#pragma unroll
    for (int m = 0; m < 4; m++) {
        int row0 = mbase + warpM * 64 + m * 16 + g;
#pragma unroll
        for (int n = 0; n < 4; n++) {
            int col = nbase + warpN * 32 + n * 8 + cp;
            float b0 = 0.f, b1 = 0.f;
            if (BIAS) { b0 = bias[col]; b1 = bias[col + 1]; }
            float2 v0 = make_float2(acc[m][n][0] + b0, acc[m][n][1] + b1);
            float2 v1 = make_float2(acc[m][n][2] + b0, acc[m][n][3] + b1);
            *(float2*)(C + (size_t)row0 * Nc + col) = v0;
            *(float2*)(C + (size_t)(row0 + 8) * Nc + col) = v1;
        }
    }
}

// ---------------------------------------------------------------------------
// l2norm v2: normalize q/k per 64-group and emit bf16 hi/lo in per-head layout
// g_qn*[bh][n][0..63]=q_n, [64..127]=k_n.  One warp per (token, head).
// ---------------------------------------------------------------------------
__global__ __launch_bounds__(256) void l2norm2_kernel(const float* __restrict__ qk)
{
    int w = blockIdx.x * 8 + (threadIdx.x >> 5);   // 0..131071
    int lane = threadIdx.x & 31;
    int tok = w >> 4;
    int h = w & 15;
    int b = tok >> 11;
    int n = tok & 2047;

    const float* qp = qk + (size_t)tok * (2 * CC) + h * HD;
    const float* kp = qp + CC;
    float q0 = qp[lane], q1 = qp[lane + 32];
    float k0 = kp[lane], k1 = kp[lane + 32];
    float sq = q0 * q0 + q1 * q1;
    float sk = k0 * k0 + k1 * k1;
#pragma unroll
    for (int off = 16; off; off >>= 1) {
        sq += __shfl_xor_sync(0xffffffffu, sq, off);
        sk += __shfl_xor_sync(0xffffffffu, sk, off);
    }
    float iq = 1.0f / fmaxf(sqrtf(sq), 1e-12f);
    float ik = 1.0f / fmaxf(sqrtf(sk), 1e-12f);
    q0 *= iq; q1 *= iq; k0 *= ik; k1 *= ik;

    size_t base = ((size_t)(b * HH + h) * NN + n) * 128;
    __nv_bfloat16 h0 = __float2bfloat16(q0);
    __nv_bfloat16 h1 = __float2bfloat16(q1);
    __nv_bfloat16 h2 = __float2bfloat16(k0);
    __nv_bfloat16 h3 = __float2bfloat16(k1);
    g_qnh[base + lane]       = h0;
    g_qnh[base + lane + 32]  = h1;
    g_qnh[base + 64 + lane]  = h2;
    g_qnh[base + 96 + lane]  = h3;
    g_qnl[base + lane]       = __float2bfloat16(q0 - __bfloat162float(h0));
    g_qnl[base + lane + 32]  = __float2bfloat16(q1 - __bfloat162float(h1));
    g_qnl[base + 64 + lane]  = __float2bfloat16(k0 - __bfloat162float(h2));
    g_qnl[base + 96 + lane]  = __float2bfloat16(k1 - __bfloat162float(h3));
}

// ---------------------------------------------------------------------------
// genw v2: per (b,h) fold subsampled low-rank weights with cw_w, emit combined
// weight matrix BW[o][d] (d<64: AE[d][o], d>=64: AR[d-64][o]) as bf16 hi/lo.
// ---------------------------------------------------------------------------
__global__ __launch_bounds__(256) void genw_kernel(
    const float* __restrict__ x, const float* __restrict__ we,
    const float* __restrict__ wr, const float* __restrict__ cw_w)
{
    int bh = blockIdx.x;
    int b = bh >> 4, h = bh & 15;
    __shared__ int   idx_s[RR];
    __shared__ float web[HD][LR], wrb[HD][LR];
    int t = threadIdx.x;

    if (t < RR) idx_s[t] = (int)((double)t * (double)(NN - 1) / (double)(RR - 1));
    __syncthreads();

    for (int it = t; it < HD * LR; it += 256) {
        int d = it / LR, e = it % LR;
        float se = 0.f, sr = 0.f;
        for (int r = 0; r < RR; r++) {
            float xv = x[((size_t)b * NN + idx_s[r]) * CC + h * HD + d];
            se += xv * we[((size_t)h * RR + r) * LR + e];
            sr += xv * wr[((size_t)h * RR + r) * LR + e];
        }
        web[d][e] = se;
        wrb[d][e] = sr;
    }
    __syncthreads();

    __nv_bfloat16* bwh = g_bwh + (size_t)bh * HD * 128;
    __nv_bfloat16* bwl = g_bwl + (size_t)bh * HD * 128;
    for (int it = t; it < HD * HD; it += 256) {
        int d = it >> 6, o = it & 63;
        float ae = 0.f, ar = 0.f;
#pragma unroll
        for (int e = 0; e < LR; e++) {
            ae += web[d][e] * cw_w[o * (2 * LR) + e];
            ar += wrb[d][e] * cw_w[o * (2 * LR) + LR + e];
        }
        __nv_bfloat16 ha = __float2bfloat16(ae);
        __nv_bfloat16 hr = __float2bfloat16(ar);
        bwh[o * 128 + d]      = ha;
        bwh[o * 128 + 64 + d] = hr;
        bwl[o * 128 + d]      = __float2bfloat16(ae - __bfloat162float(ha));
        bwl[o * 128 + 64 + d] = __float2bfloat16(ar - __bfloat162float(hr));
    }
}

// ---------------------------------------------------------------------------
// score via HMMA: per bh, attn_tile[256,64] = QK[256,128] @ BW[64,128]^T + cw_b
// 3-term bf16 split; output written directly as bf16 hi/lo (feeds GEMM2).
// ---------------------------------------------------------------------------
#define SC_SMEM ((2 * 256 * LDT + 2 * 64 * LDT) * 2)

__global__ __launch_bounds__(256, 2) void score_mma_kernel(const float* __restrict__ cw_b)
{
    extern __shared__ __nv_bfloat16 ssm[];
    __nv_bfloat16* sAh = ssm;                      // 256*40
    __nv_bfloat16* sAl = ssm + 256 * LDT;
    __nv_bfloat16* sBh = ssm + 2 * 256 * LDT;      // 64*40
    __nv_bfloat16* sBl = ssm + 2 * 256 * LDT + 64 * LDT;

    const int t = threadIdx.x;
    const int lane = t & 31, wid = t >> 5;
    const int warpM = wid >> 1;
    const int warpN = wid & 1;
    const int tileM = blockIdx.x;      // 0..7 (256-token tiles)
    const int bh = blockIdx.y;
    const int b = bh >> 4, h = bh & 15;

    const __nv_bfloat16* Abh = g_qnh + ((size_t)bh * NN + tileM * 256) * 128;
    const __nv_bfloat16* Abl = g_qnl + ((size_t)bh * NN + tileM * 256) * 128;
    const __nv_bfloat16* Bbh = g_bwh + (size_t)bh * HD * 128;
    const __nv_bfloat16* Bbl = g_bwl + (size_t)bh * HD * 128;

    const uint32_t smb = smem_u32(ssm);
    const uint32_t offAl = 256 * LDT * 2;
    const uint32_t offBh = 2 * 256 * LDT * 2;
    const uint32_t offBl = offBh + 64 * LDT * 2;

    float acc[4][4][4];
#pragma unroll
    for (int m = 0; m < 4; m++)
#pragma unroll
        for (int n = 0; n < 4; n++)
#pragma unroll
            for (int j = 0; j < 4; j++) acc[m][n][j] = 0.f;

    const int a_row = warpM * 64 + (lane & 15);
    const int a_colh = (lane >> 4) << 3;
    const int b_row = warpN * 32 + ((lane >> 4) << 3) + (lane & 7);
    const int b_colh = ((lane >> 3) & 1) << 3;

    for (int ck = 0; ck < 4; ck++) {
        int kt = ck * 32;
        if (ck) __syncthreads();
        // A: 1024 x 16B per operand
#pragma unroll
        for (int j = 0; j < 4; j++) {
            int idx = t + j * 256;
            int row = idx >> 2, c = idx & 3;
            *(uint4*)(sAh + row * LDT + c * 8) = *(const uint4*)(Abh + (size_t)row * 128 + kt + c * 8);
            *(uint4*)(sAl + row * LDT + c * 8) = *(const uint4*)(Abl + (size_t)row * 128 + kt + c * 8);
        }
        // B: 256 x 16B per operand
        {
            int row = t >> 2, c = t & 3;
            if (row < 64) {
                *(uint4*)(sBh + row * LDT + c * 8) = *(const uint4*)(Bbh + (size_t)row * 128 + kt + c * 8);
                *(uint4*)(sBl + row * LDT + c * 8) = *(const uint4*)(Bbl + (size_t)row * 128 + kt + c * 8);
            }
        }
        __syncthreads();

#pragma unroll
        for (int kk = 0; kk < 32; kk += 16) {
            uint32_t ah[4][4], al[4][4];
#pragma unroll
            for (int m = 0; m < 4; m++) {
                uint32_t off = ((a_row + m * 16) * LDT + kk + a_colh) * 2;
                ldm_x4(ah[m], smb + off);
                ldm_x4(al[m], smb + offAl + off);
            }
            uint32_t bhf[2][4], blf[2][4];
#pragma unroll
            for (int p = 0; p < 2; p++) {
                uint32_t off = ((b_row + p * 16) * LDT + kk + b_colh) * 2;
                ldm_x4(bhf[p], smb + offBh + off);
                ldm_x4(blf[p], smb + offBl + off);
            }
#pragma unroll
            for (int m = 0; m < 4; m++) {
#pragma unroll
                for (int n = 0; n < 4; n++) {
                    const uint32_t* bh2 = &bhf[n >> 1][(n & 1) * 2];
                    const uint32_t* bl2 = &blf[n >> 1][(n & 1) * 2];
                    mma_bf16(acc[m][n], ah[m], bh2);
                    mma_bf16(acc[m][n], ah[m], bl2);
                    mma_bf16(acc[m][n], al[m], bh2);
                }
            }
        }
    }

    // epilogue: +cw_b, split to bf16 hi/lo, store into attn (g_ah/g_al)
    const int g = lane >> 2;
    const int cp = (lane & 3) * 2;
#pragma unroll
    for (int m = 0; m < 4; m++) {
        int n_tok = tileM * 256 + warpM * 64 + m * 16 + g;   // 0..2047
#pragma unroll
        for (int n = 0; n < 4; n++) {
            int col = warpN * 32 + n * 8 + cp;               // 0..63
            float b0 = cw_b[col], b1 = cw_b[col + 1];
            size_t r0 = ((size_t)(b * NN + n_tok)) * CC + h * HD + col;
            size_t r1 = ((size_t)(b * NN + n_tok + 8)) * CC + h * HD + col;
            split_store2(acc[m][n][0] + b0, acc[m][n][1] + b1, g_ah + r0, g_al + r0);
            split_store2(acc[m][n][2] + b0, acc[m][n][3] + b1, g_ah + r1, g_al + r1);
        }
    }
}

// ---------------------------------------------------------------------------
extern "C" void kernel_launch(void* const* d_in, const int* in_sizes, int n_in,
                              void* d_out, int out_size)
{
    const float* x      = (const float*)d_in[0];
    const float* qk_w   = (const float*)d_in[1];
    const float* proj_w = (const float*)d_in[2];
    const float* proj_b = (const float*)d_in[3];
    const float* we     = (const float*)d_in[4];
    const float* wr     = (const float*)d_in[5];
    const float* cw_w   = (const float*)d_in[6];
    const float* cw_b   = (const float*)d_in[7];
    float* out = (float*)d_out;

    void *p_qk, *p_xh, *p_xl, *p_qkwh, *p_qkwl, *p_pwh, *p_pwl, *p_ah, *p_al;
    cudaGetSymbolAddress(&p_qk, g_qk);
    cudaGetSymbolAddress(&p_xh, g_xh);
    cudaGetSymbolAddress(&p_xl, g_xl);
    cudaGetSymbolAddress(&p_qkwh, g_qkwh);
    cudaGetSymbolAddress(&p_qkwl, g_qkwl);
    cudaGetSymbolAddress(&p_pwh, g_pwh);
    cudaGetSymbolAddress(&p_pwl, g_pwl);
    cudaGetSymbolAddress(&p_ah, g_ah);
    cudaGetSymbolAddress(&p_al, g_al);
    float* qk = (float*)p_qk;

    cudaFuncSetAttribute(gemm3h_kernel<false>, cudaFuncAttributeMaxDynamicSharedMemorySize, GEMM_SMEM);
    cudaFuncSetAttribute(gemm3h_kernel<true>,  cudaFuncAttributeMaxDynamicSharedMemorySize, GEMM_SMEM);
    cudaFuncSetAttribute(score_mma_kernel, cudaFuncAttributeMaxDynamicSharedMemorySize, SC_SMEM);

    // 0) split inputs to bf16 hi/lo
    split_kernel<<<(M_TOK * CC / 4) / 256, 256>>>(x, (__nv_bfloat16*)p_xh, (__nv_bfloat16*)p_xl, M_TOK * CC / 4);
    split_kernel<<<(2 * CC * CC / 4) / 256, 256>>>(qk_w, (__nv_bfloat16*)p_qkwh, (__nv_bfloat16*)p_qkwl, 2 * CC * CC / 4);
    split_kernel<<<(CC * CC / 4) / 256, 256>>>(proj_w, (__nv_bfloat16*)p_pwh, (__nv_bfloat16*)p_pwl, CC * CC / 4);

    // 1) qk = x @ qk_w^T  (HMMA, bf16 x3, cp.async, 2 CTAs/SM)
    gemm3h_kernel<false><<<dim3(2 * CC / 128, M_TOK / 128), 256, GEMM_SMEM>>>(
        (const __nv_bfloat16*)p_xh, (const __nv_bfloat16*)p_xl,
        (const __nv_bfloat16*)p_qkwh, (const __nv_bfloat16*)p_qkwl,
        nullptr, qk, M_TOK, 2 * CC, CC);

    // 2) normalize q/k -> bf16 hi/lo per-head layout
    l2norm2_kernel<<<(M_TOK * HH) / 8, 256>>>(qk);

    // 3) fold low-rank weights -> BW bf16 hi/lo
    genw_kernel<<<BB * HH, 256>>>(x, we, wr, cw_w);

    // 4) attn = [q|k] @ BW^T + cw_b  (HMMA), output split bf16 hi/lo
    score_mma_kernel<<<dim3(NN / 256, BB * HH), 256, SC_SMEM>>>(cw_b);

    // 5) out = attn @ proj_w^T + proj_b  (HMMA, bf16 x3, cp.async, 2 CTAs/SM)
    gemm3h_kernel<true><<<dim3(CC / 128, M_TOK / 128), 256, GEMM_SMEM>>>(
        (const __nv_bfloat16*)p_ah, (const __nv_bfloat16*)p_al,
        (const __nv_bfloat16*)p_pwh, (const __nv_bfloat16*)p_pwl,
        proj_b, out, M_TOK, CC, CC);
}